// round 1
// baseline (speedup 1.0000x reference)
#include <cuda_runtime.h>
#include <cuda_bf16.h>
#include <cstdint>
#include <math.h>

#define NTOK 8192
#define DIM 1024
#define HID 4096
#define NEXP 8
#define BM 128
#define BK 32
#define BN1 64
#define BN2 128
#define MAXT 72

// ---- persistent device scratch (no runtime allocation allowed) ----
__device__ int g_order[NTOK];
__device__ int g_tile_expert[MAXT];
__device__ int g_tile_row0[MAXT];
__device__ int g_tile_rows[MAXT];
__device__ int g_ntiles;
// padded by BM rows so tiles overhanging the last segment stay in-bounds;
// unwritten rows are static-zero and their outputs are never stored.
__device__ float g_hbuf[(size_t)(NTOK + BM) * HID];

// ---------------------------------------------------------------------------
// Routing: count tokens per expert, build sorted order + per-expert tile table
// ---------------------------------------------------------------------------
__global__ void route_kernel(const int* __restrict__ rm) {
    __shared__ int cnt[NEXP], off[NEXP], cur[NEXP];
    int tid = threadIdx.x;
    if (tid < NEXP) cnt[tid] = 0;
    __syncthreads();
    for (int i = tid; i < NTOK; i += blockDim.x) atomicAdd(&cnt[rm[i]], 1);
    __syncthreads();
    if (tid == 0) {
        int run = 0, nt = 0;
        for (int e = 0; e < NEXP; e++) {
            off[e] = run;
            int rem = cnt[e], r = run;
            while (rem > 0) {
                g_tile_expert[nt] = e;
                g_tile_row0[nt] = r;
                g_tile_rows[nt] = rem < BM ? rem : BM;
                r += BM; rem -= BM; nt++;
            }
            run += cnt[e];
        }
        g_ntiles = nt;
    }
    __syncthreads();
    if (tid < NEXP) cur[tid] = off[tid];
    __syncthreads();
    for (int i = tid; i < NTOK; i += blockDim.x) {
        int p = atomicAdd(&cur[rm[i]], 1);
        g_order[p] = i;
    }
}

// ---------------------------------------------------------------------------
// helpers
// ---------------------------------------------------------------------------
__device__ __forceinline__ float to_tf32(float f) {
    asm("cvt.rna.tf32.f32 %0, %0;" : "+f"(f));
    return f;
}

__device__ __forceinline__ void mma_tf32(float c[4], const uint32_t a[4], const uint32_t b[2]) {
    asm volatile(
        "mma.sync.aligned.m16n8k8.row.col.f32.tf32.tf32.f32 "
        "{%0,%1,%2,%3}, {%4,%5,%6,%7}, {%8,%9}, {%0,%1,%2,%3};"
        : "+f"(c[0]), "+f"(c[1]), "+f"(c[2]), "+f"(c[3])
        : "r"(a[0]), "r"(a[1]), "r"(a[2]), "r"(a[3]), "r"(b[0]), "r"(b[1]));
}

// ---------------------------------------------------------------------------
// GEMM1: h = silu(X@Wg + bg) * (X@Wi + bi)   per expert tile
// block tile 128(M) x 64(N) x both matrices, 8 warps (2M x 4N), warp 64x16
// ---------------------------------------------------------------------------
__global__ __launch_bounds__(256, 2) void gemm1_kernel(
    const float* __restrict__ x,
    const float* __restrict__ Wg, const float* __restrict__ bg,
    const float* __restrict__ Wi, const float* __restrict__ bi)
{
    int mt = blockIdx.x;
    if (mt >= g_ntiles) return;
    int e    = g_tile_expert[mt];
    int row0 = g_tile_row0[mt];
    int rows = g_tile_rows[mt];
    int n0   = blockIdx.y * BN1;

    __shared__ float As[BM][BK + 4];
    __shared__ float Bgs[BK][BN1 + 8];
    __shared__ float Bis[BK][BN1 + 8];

    int tid = threadIdx.x;
    int lane = tid & 31, wid = tid >> 5;
    int wm = wid & 1, wn = wid >> 1;
    int gq = lane >> 2, q = lane & 3;

    float cg[4][2][4], ci[4][2][4];
#pragma unroll
    for (int i = 0; i < 4; i++)
#pragma unroll
        for (int j = 0; j < 2; j++)
#pragma unroll
            for (int k = 0; k < 4; k++) { cg[i][j][k] = 0.f; ci[i][j][k] = 0.f; }

    // A-load mapping: 128x32 tile, float4 per thread x4 rows
    int ar = tid >> 3;
    int ac = (tid & 7) * 4;
    long tokoff[4];
#pragma unroll
    for (int j = 0; j < 4; j++) {
        int r = ar + j * 32;
        tokoff[j] = (r < rows) ? (long)g_order[row0 + r] * DIM : -1;
    }
    // B-load mapping: 32x64 tile per matrix
    int br = tid >> 4;
    int bc = (tid & 15) * 4;
    const float* wg_base = Wg + (size_t)e * DIM * HID + n0;
    const float* wi_base = Wi + (size_t)e * DIM * HID + n0;

    for (int k0 = 0; k0 < DIM; k0 += BK) {
#pragma unroll
        for (int j = 0; j < 4; j++) {
            float4 v = make_float4(0.f, 0.f, 0.f, 0.f);
            if (tokoff[j] >= 0) v = *(const float4*)(x + tokoff[j] + k0 + ac);
            v.x = to_tf32(v.x); v.y = to_tf32(v.y); v.z = to_tf32(v.z); v.w = to_tf32(v.w);
            *(float4*)&As[ar + j * 32][ac] = v;
        }
#pragma unroll
        for (int j = 0; j < 2; j++) {
            int kk = br + j * 16;
            float4 v = *(const float4*)(wg_base + (size_t)(k0 + kk) * HID + bc);
            v.x = to_tf32(v.x); v.y = to_tf32(v.y); v.z = to_tf32(v.z); v.w = to_tf32(v.w);
            *(float4*)&Bgs[kk][bc] = v;
            float4 w = *(const float4*)(wi_base + (size_t)(k0 + kk) * HID + bc);
            w.x = to_tf32(w.x); w.y = to_tf32(w.y); w.z = to_tf32(w.z); w.w = to_tf32(w.w);
            *(float4*)&Bis[kk][bc] = w;
        }
        __syncthreads();

#pragma unroll
        for (int ks = 0; ks < 4; ks++) {
            uint32_t a[4][4], bgf[2][2], bif[2][2];
#pragma unroll
            for (int mf = 0; mf < 4; mf++) {
                int rr = wm * 64 + mf * 16 + gq;
                a[mf][0] = __float_as_uint(As[rr][ks * 8 + q]);
                a[mf][1] = __float_as_uint(As[rr + 8][ks * 8 + q]);
                a[mf][2] = __float_as_uint(As[rr][ks * 8 + q + 4]);
                a[mf][3] = __float_as_uint(As[rr + 8][ks * 8 + q + 4]);
            }
#pragma unroll
            for (int nf = 0; nf < 2; nf++) {
                int cc = wn * 16 + nf * 8 + gq;
                bgf[nf][0] = __float_as_uint(Bgs[ks * 8 + q][cc]);
                bgf[nf][1] = __float_as_uint(Bgs[ks * 8 + q + 4][cc]);
                bif[nf][0] = __float_as_uint(Bis[ks * 8 + q][cc]);
                bif[nf][1] = __float_as_uint(Bis[ks * 8 + q + 4][cc]);
            }
#pragma unroll
            for (int mf = 0; mf < 4; mf++)
#pragma unroll
                for (int nf = 0; nf < 2; nf++) {
                    mma_tf32(cg[mf][nf], a[mf], bgf[nf]);
                    mma_tf32(ci[mf][nf], a[mf], bif[nf]);
                }
        }
        __syncthreads();
    }

    // epilogue: silu(gate)*in -> g_hbuf (sorted-row layout)
#pragma unroll
    for (int nf = 0; nf < 2; nf++) {
        int ccol = n0 + wn * 16 + nf * 8 + q * 2;
        float bg0 = bg[e * HID + ccol], bg1 = bg[e * HID + ccol + 1];
        float bi0 = bi[e * HID + ccol], bi1 = bi[e * HID + ccol + 1];
#pragma unroll
        for (int mf = 0; mf < 4; mf++) {
            int rl = wm * 64 + mf * 16 + gq;
#pragma unroll
            for (int h = 0; h < 2; h++) {
                int ri = rl + h * 8;
                if (ri < rows) {
                    float g0 = cg[mf][nf][h * 2 + 0] + bg0;
                    float g1 = cg[mf][nf][h * 2 + 1] + bg1;
                    float i0 = ci[mf][nf][h * 2 + 0] + bi0;
                    float i1 = ci[mf][nf][h * 2 + 1] + bi1;
                    float h0 = g0 * i0 / (1.f + __expf(-g0));
                    float h1 = g1 * i1 / (1.f + __expf(-g1));
                    *(float2*)&g_hbuf[(size_t)(row0 + ri) * HID + ccol] = make_float2(h0, h1);
                }
            }
        }
    }
}

// ---------------------------------------------------------------------------
// GEMM2: out[token] = h @ Wo[e] + bo[e]   (scatter store)
// block tile 128(M) x 128(N), 8 warps (2M x 4N), warp 64x32
// ---------------------------------------------------------------------------
__global__ __launch_bounds__(256, 2) void gemm2_kernel(
    const float* __restrict__ Wo, const float* __restrict__ bo, float* __restrict__ out)
{
    int mt = blockIdx.x;
    if (mt >= g_ntiles) return;
    int e    = g_tile_expert[mt];
    int row0 = g_tile_row0[mt];
    int rows = g_tile_rows[mt];
    int n0   = blockIdx.y * BN2;

    __shared__ float As[BM][BK + 4];
    __shared__ float Bs[BK][BN2 + 8];

    int tid = threadIdx.x;
    int lane = tid & 31, wid = tid >> 5;
    int wm = wid & 1, wn = wid >> 1;
    int gq = lane >> 2, q = lane & 3;

    float c[4][4][4];
#pragma unroll
    for (int i = 0; i < 4; i++)
#pragma unroll
        for (int j = 0; j < 4; j++)
#pragma unroll
            for (int k = 0; k < 4; k++) c[i][j][k] = 0.f;

    int ar = tid >> 3;
    int ac = (tid & 7) * 4;
    int br = tid >> 5;
    int bc = (tid & 31) * 4;
    const float* wo_base = Wo + (size_t)e * HID * DIM + n0;
    const float* a_base = g_hbuf + (size_t)row0 * HID;

    for (int k0 = 0; k0 < HID; k0 += BK) {
#pragma unroll
        for (int j = 0; j < 4; j++) {
            float4 v = *(const float4*)(a_base + (size_t)(ar + j * 32) * HID + k0 + ac);
            v.x = to_tf32(v.x); v.y = to_tf32(v.y); v.z = to_tf32(v.z); v.w = to_tf32(v.w);
            *(float4*)&As[ar + j * 32][ac] = v;
        }
#pragma unroll
        for (int j = 0; j < 4; j++) {
            int kk = br + j * 8;
            float4 v = *(const float4*)(wo_base + (size_t)(k0 + kk) * DIM + bc);
            v.x = to_tf32(v.x); v.y = to_tf32(v.y); v.z = to_tf32(v.z); v.w = to_tf32(v.w);
            *(float4*)&Bs[kk][bc] = v;
        }
        __syncthreads();

#pragma unroll
        for (int ks = 0; ks < 4; ks++) {
            uint32_t a[4][4], b[4][2];
#pragma unroll
            for (int mf = 0; mf < 4; mf++) {
                int rr = wm * 64 + mf * 16 + gq;
                a[mf][0] = __float_as_uint(As[rr][ks * 8 + q]);
                a[mf][1] = __float_as_uint(As[rr + 8][ks * 8 + q]);
                a[mf][2] = __float_as_uint(As[rr][ks * 8 + q + 4]);
                a[mf][3] = __float_as_uint(As[rr + 8][ks * 8 + q + 4]);
            }
#pragma unroll
            for (int nf = 0; nf < 4; nf++) {
                int cc = wn * 32 + nf * 8 + gq;
                b[nf][0] = __float_as_uint(Bs[ks * 8 + q][cc]);
                b[nf][1] = __float_as_uint(Bs[ks * 8 + q + 4][cc]);
            }
#pragma unroll
            for (int mf = 0; mf < 4; mf++)
#pragma unroll
                for (int nf = 0; nf < 4; nf++)
                    mma_tf32(c[mf][nf], a[mf], b[nf]);
        }
        __syncthreads();
    }

    // epilogue: scatter to out[token] with bias
#pragma unroll
    for (int mf = 0; mf < 4; mf++) {
        int rl = wm * 64 + mf * 16 + gq;
#pragma unroll
        for (int h = 0; h < 2; h++) {
            int ri = rl + h * 8;
            if (ri < rows) {
                int tok = g_order[row0 + ri];
#pragma unroll
                for (int nf = 0; nf < 4; nf++) {
                    int ccol = n0 + wn * 32 + nf * 8 + q * 2;
                    float o0 = c[mf][nf][h * 2 + 0] + bo[e * DIM + ccol];
                    float o1 = c[mf][nf][h * 2 + 1] + bo[e * DIM + ccol + 1];
                    *(float2*)&out[(size_t)tok * DIM + ccol] = make_float2(o0, o1);
                }
            }
        }
    }
}

// ---------------------------------------------------------------------------
extern "C" void kernel_launch(void* const* d_in, const int* in_sizes, int n_in,
                              void* d_out, int out_size) {
    const float* x   = (const float*)d_in[0];
    const int*   rm  = (const int*)d_in[1];
    const float* Win = (const float*)d_in[2];
    const float* bin = (const float*)d_in[3];
    const float* Wgt = (const float*)d_in[4];
    const float* bgt = (const float*)d_in[5];
    const float* Wo  = (const float*)d_in[6];
    const float* bo  = (const float*)d_in[7];
    float* out = (float*)d_out;

    route_kernel<<<1, 256>>>(rm);
    gemm1_kernel<<<dim3(MAXT, HID / BN1), 256>>>(x, Wgt, bgt, Win, bin);
    gemm2_kernel<<<dim3(MAXT, DIM / BN2), 256>>>(Wo, bo, out);
}